// round 16
// baseline (speedup 1.0000x reference)
#include <cuda_runtime.h>
#include <math.h>

#define NRES 768
#define CSD  384
#define CZD  128
#define NHD  12
#define INF_ 100000.0f

typedef unsigned long long u64;

// ---------------- packed f32x2 helpers ----------------
__device__ __forceinline__ void ffma2(u64& d, u64 a, u64 b) {
    asm("fma.rn.f32x2 %0, %1, %2, %0;" : "+l"(d) : "l"(a), "l"(b));
}
__device__ __forceinline__ u64 dup2(float x) {
    u64 r; asm("mov.b64 %0, {%1, %1};" : "=l"(r) : "f"(x)); return r;
}
__device__ __forceinline__ u64 pk2(float lo, float hi) {
    u64 r; asm("mov.b64 %0, {%1, %2};" : "=l"(r) : "f"(lo), "f"(hi)); return r;
}
__device__ __forceinline__ float2 up2(u64 v) {
    float lo, hi; asm("mov.b64 {%0, %1}, %2;" : "=f"(lo), "=f"(hi) : "l"(v));
    return make_float2(lo, hi);
}
// ---------------- cp.async helpers ----------------
__device__ __forceinline__ void cpa16(void* dst, const void* src) {
    unsigned sdst = (unsigned)__cvta_generic_to_shared(dst);
    asm volatile("cp.async.cg.shared.global [%0], [%1], 16;" :: "r"(sdst), "l"(src));
}
__device__ __forceinline__ void cpa_commit() { asm volatile("cp.async.commit_group;"); }
__device__ __forceinline__ void cpa_wait0() { asm volatile("cp.async.wait_group 0;"); }

// ---------------- scratch (device globals; no allocation) ----------------
__device__ float g_se[NRES * CSD];
__device__ float g_proj[NRES * 1152];
__device__ float g_qhat[NRES * 384];          // per n: 12 heads x 32 (28 used)
__device__ float g_khat[NRES * 384];
__device__ float g_kc[NRES * NHD];
__device__ float g_vall[NRES * NHD * 40];
__device__ float g_cat[NRES * 2112];
__device__ float g_part[4][NRES * CSD];
__device__ float g_logits[NHD * NRES * NRES]; // [i][h][j]: qk-logits, then unnormalized exp
__device__ float g_Sinv[NRES * NHD];          // 1/S per (i,h)

// =====================================================================
// fp32 GEMM with FFMA2: C = A(MxK) @ W(NxK)^T [+ bias]; 64x64 tile, BK=16.
// =====================================================================
__device__ __forceinline__ void mm16(const float* Ab, const float* Wb,
                                     int ty, int tx, u64 acc2[4][2]) {
    #pragma unroll
    for (int k = 0; k < 16; k++) {
        float4 av = *(const float4*)(Ab + k * 68 + ty * 4);
        ulonglong2 wv = *(const ulonglong2*)(Wb + k * 68 + tx * 4);
        u64 a0 = dup2(av.x), a1 = dup2(av.y), a2 = dup2(av.z), a3 = dup2(av.w);
        ffma2(acc2[0][0], a0, wv.x); ffma2(acc2[0][1], a0, wv.y);
        ffma2(acc2[1][0], a1, wv.x); ffma2(acc2[1][1], a1, wv.y);
        ffma2(acc2[2][0], a2, wv.x); ffma2(acc2[2][1], a2, wv.y);
        ffma2(acc2[3][0], a3, wv.x); ffma2(acc2[3][1], a3, wv.y);
    }
}

__global__ __launch_bounds__(256) void k_gemm64(
    const float* __restrict__ A, const float* __restrict__ W,
    const float* __restrict__ bias, float* __restrict__ C,
    int ld, int ldc, int nkt, int add_bias, int partStride)
{
    __shared__ __align__(16) float As[2][16][68];
    __shared__ __align__(16) float Ws[2][16][68];
    int t  = threadIdx.x;
    int m0 = blockIdx.y * 64, n0 = blockIdx.x * 64;
    int kt0 = blockIdx.z * nkt;
    C += (size_t)blockIdx.z * partStride;
    int lr = t >> 2, lk = (t & 3) * 4;
    const float* arow = A + (size_t)(m0 + lr) * ld + kt0 * 16 + lk;
    const float* wrow = W + (size_t)(n0 + lr) * ld + kt0 * 16 + lk;
    int tx = t & 15, ty = t >> 4;

    u64 acc2[4][2] = {};
    float4 ra = *(const float4*)arow;
    float4 rw = *(const float4*)wrow;
    int buf = 0;
    As[0][lk+0][lr]=ra.x; As[0][lk+1][lr]=ra.y; As[0][lk+2][lr]=ra.z; As[0][lk+3][lr]=ra.w;
    Ws[0][lk+0][lr]=rw.x; Ws[0][lk+1][lr]=rw.y; Ws[0][lk+2][lr]=rw.z; Ws[0][lk+3][lr]=rw.w;

    for (int kt = 0; kt < nkt - 1; kt++) {
        __syncthreads();
        ra = *(const float4*)(arow + (kt + 1) * 16);
        rw = *(const float4*)(wrow + (kt + 1) * 16);
        mm16(&As[buf][0][0], &Ws[buf][0][0], ty, tx, acc2);
        int nb = buf ^ 1;
        As[nb][lk+0][lr]=ra.x; As[nb][lk+1][lr]=ra.y; As[nb][lk+2][lr]=ra.z; As[nb][lk+3][lr]=ra.w;
        Ws[nb][lk+0][lr]=rw.x; Ws[nb][lk+1][lr]=rw.y; Ws[nb][lk+2][lr]=rw.z; Ws[nb][lk+3][lr]=rw.w;
        buf = nb;
    }
    __syncthreads();
    mm16(&As[buf][0][0], &Ws[buf][0][0], ty, tx, acc2);

    float4 bv = make_float4(0.f, 0.f, 0.f, 0.f);
    if (add_bias) bv = *(const float4*)(bias + n0 + tx * 4);
    #pragma unroll
    for (int a = 0; a < 4; a++) {
        float2 p0 = up2(acc2[a][0]), p1 = up2(acc2[a][1]);
        float4 r = make_float4(p0.x + bv.x, p0.y + bv.y, p1.x + bv.z, p1.y + bv.w);
        *(float4*)(C + (size_t)(m0 + ty * 4 + a) * ldc + n0 + tx * 4) = r;
    }
}

__device__ __forceinline__ float proj_bias(int n, const float* bq, const float* bkv,
                                           const float* bqp, const float* bkvp) {
    if (n < 192) return bq[n];
    if (n < 576) return bkv[n - 192];
    if (n < 720) return bqp[n - 576];
    return bkvp[n - 720];
}

__global__ __launch_bounds__(256) void k_gemm_proj(
    const float* __restrict__ wq,  const float* __restrict__ bq,
    const float* __restrict__ wkv, const float* __restrict__ bkv,
    const float* __restrict__ wqp, const float* __restrict__ bqp,
    const float* __restrict__ wkvp,const float* __restrict__ bkvp)
{
    __shared__ __align__(16) float As[2][16][68];
    __shared__ __align__(16) float Ws[2][16][68];
    int t  = threadIdx.x;
    int m0 = blockIdx.y * 64, n0 = blockIdx.x * 64;
    int lr = t >> 2, lk = (t & 3) * 4;
    const float* arow = g_se + (size_t)(m0 + lr) * 384 + lk;
    int n = n0 + lr;
    const float* wbase; int nl;
    if      (n < 192) { wbase = wq;   nl = n; }
    else if (n < 576) { wbase = wkv;  nl = n - 192; }
    else if (n < 720) { wbase = wqp;  nl = n - 576; }
    else              { wbase = wkvp; nl = n - 720; }
    const float* wrow = wbase + (size_t)nl * 384 + lk;
    int tx = t & 15, ty = t >> 4;

    u64 acc2[4][2] = {};
    float4 ra = *(const float4*)arow;
    float4 rw = *(const float4*)wrow;
    int buf = 0;
    As[0][lk+0][lr]=ra.x; As[0][lk+1][lr]=ra.y; As[0][lk+2][lr]=ra.z; As[0][lk+3][lr]=ra.w;
    Ws[0][lk+0][lr]=rw.x; Ws[0][lk+1][lr]=rw.y; Ws[0][lk+2][lr]=rw.z; Ws[0][lk+3][lr]=rw.w;

    const int nkt = 24;
    for (int kt = 0; kt < nkt - 1; kt++) {
        __syncthreads();
        ra = *(const float4*)(arow + (kt + 1) * 16);
        rw = *(const float4*)(wrow + (kt + 1) * 16);
        mm16(&As[buf][0][0], &Ws[buf][0][0], ty, tx, acc2);
        int nb = buf ^ 1;
        As[nb][lk+0][lr]=ra.x; As[nb][lk+1][lr]=ra.y; As[nb][lk+2][lr]=ra.z; As[nb][lk+3][lr]=ra.w;
        Ws[nb][lk+0][lr]=rw.x; Ws[nb][lk+1][lr]=rw.y; Ws[nb][lk+2][lr]=rw.z; Ws[nb][lk+3][lr]=rw.w;
        buf = nb;
    }
    __syncthreads();
    mm16(&As[buf][0][0], &Ws[buf][0][0], ty, tx, acc2);

    int nc = n0 + tx * 4;
    float4 bv = make_float4(proj_bias(nc + 0, bq, bkv, bqp, bkvp),
                            proj_bias(nc + 1, bq, bkv, bqp, bkvp),
                            proj_bias(nc + 2, bq, bkv, bqp, bkvp),
                            proj_bias(nc + 3, bq, bkv, bqp, bkvp));
    #pragma unroll
    for (int a = 0; a < 4; a++) {
        float2 p0 = up2(acc2[a][0]), p1 = up2(acc2[a][1]);
        float4 r = make_float4(p0.x + bv.x, p0.y + bv.y, p1.x + bv.z, p1.y + bv.w);
        *(float4*)(g_proj + (size_t)(m0 + ty * 4 + a) * 1152 + nc) = r;
    }
}

__global__ void k_combine(const float* __restrict__ bout, float* __restrict__ out) {
    int i = blockIdx.x * 256 + threadIdx.x;
    out[i] = g_part[0][i] + g_part[1][i] + g_part[2][i] + g_part[3][i] + bout[i % 384];
}

// ---------------- LayerNorm over split-K partials ----------------
__global__ void k_ln(const float* __restrict__ bexp,
                     const float* __restrict__ gamma, const float* __restrict__ beta) {
    int n = blockIdx.x, t = threadIdx.x;
    const float* P0 = g_part[0] + (size_t)n * CSD;
    const float* P1 = g_part[1] + (size_t)n * CSD;
    float x0 = P0[t]       + P1[t]       + bexp[t];
    float x1 = P0[t + 128] + P1[t + 128] + bexp[t + 128];
    float x2 = P0[t + 256] + P1[t + 256] + bexp[t + 256];
    float s1 = x0 + x1 + x2;
    float s2 = x0 * x0 + x1 * x1 + x2 * x2;
    __shared__ float r1[4], r2[4];
    #pragma unroll
    for (int o = 16; o; o >>= 1) {
        s1 += __shfl_xor_sync(0xffffffffu, s1, o);
        s2 += __shfl_xor_sync(0xffffffffu, s2, o);
    }
    if ((t & 31) == 0) { r1[t >> 5] = s1; r2[t >> 5] = s2; }
    __syncthreads();
    float ts1 = r1[0] + r1[1] + r1[2] + r1[3];
    float ts2 = r2[0] + r2[1] + r2[2] + r2[3];
    float mu  = ts1 * (1.f / 384.f);
    float var = ts2 * (1.f / 384.f) - mu * mu;
    float inv = rsqrtf(var + 1e-5f);
    float* row = g_se + (size_t)n * CSD;
    row[t]       = (x0 - mu) * inv * gamma[t]       + beta[t];
    row[t + 128] = (x1 - mu) * inv * gamma[t + 128] + beta[t + 128];
    row[t + 256] = (x2 - mu) * inv * gamma[t + 256] + beta[t + 256];
}

// ---------------- assemble (vectorized LDG.128/STG.128) ----------------
__global__ void k_assemble(const float* __restrict__ r_rot, const float* __restrict__ r_trans,
                           const float* __restrict__ head_w) {
    int gw   = blockIdx.x * 8 + (threadIdx.x >> 5);
    int lane = threadIdx.x & 31;
    if (gw >= NRES || lane >= NHD) return;
    int n = gw, h = lane;
    float rot[9], t0[3];
    #pragma unroll
    for (int i = 0; i < 9; i++) rot[i] = r_rot[n * 45 + i];
    #pragma unroll
    for (int i = 0; i < 3; i++) t0[i] = r_trans[n * 15 + i];
    float hw = log1pf(expf(head_w[h])) * rsqrtf(54.0f);
    const float c1 = rsqrtf(48.0f);
    const float* P = g_proj + (size_t)n * 1152;
    float* qh = g_qhat + (size_t)n * 384 + h * 32;
    float* kh = g_khat + (size_t)n * 384 + h * 32;
    float* va = g_vall + ((size_t)n * NHD + h) * 40;
    #pragma unroll
    for (int c4 = 0; c4 < 4; c4++) {
        float4 q = *(const float4*)(P + h * 16 + c4 * 4);
        q.x *= c1; q.y *= c1; q.z *= c1; q.w *= c1;
        *(float4*)(qh + c4 * 4) = q;
        *(float4*)(kh + c4 * 4) = *(const float4*)(P + 192 + h * 32 + c4 * 4);
        *(float4*)(va + c4 * 4) = *(const float4*)(P + 192 + h * 32 + 16 + c4 * 4);
    }
    // q points: 4 pts contiguous per dim
    {
        float4 l0 = *(const float4*)(P + 576 + h * 4);
        float4 l1 = *(const float4*)(P + 576 + 48 + h * 4);
        float4 l2 = *(const float4*)(P + 576 + 96 + h * 4);
        float a0[4] = {l0.x, l0.y, l0.z, l0.w};
        float a1[4] = {l1.x, l1.y, l1.z, l1.w};
        float a2[4] = {l2.x, l2.y, l2.z, l2.w};
        float qp[12];
        #pragma unroll
        for (int pp = 0; pp < 4; pp++)
            #pragma unroll
            for (int i = 0; i < 3; i++)
                qp[pp * 3 + i] = hw * (rot[i*3]*a0[pp] + rot[i*3+1]*a1[pp] + rot[i*3+2]*a2[pp] + t0[i]);
        *(float4*)(qh + 16) = *(float4*)(qp);
        *(float4*)(qh + 20) = *(float4*)(qp + 4);
        *(float4*)(qh + 24) = *(float4*)(qp + 8);
    }
    // kv points: 12 pts contiguous per dim
    {
        float kv0[12], kv1[12], kv2[12];
        #pragma unroll
        for (int c4 = 0; c4 < 3; c4++) {
            *(float4*)(kv0 + c4 * 4) = *(const float4*)(P + 720 +   0 + h * 12 + c4 * 4);
            *(float4*)(kv1 + c4 * 4) = *(const float4*)(P + 720 + 144 + h * 12 + c4 * 4);
            *(float4*)(kv2 + c4 * 4) = *(const float4*)(P + 720 + 288 + h * 12 + c4 * 4);
        }
        float kp[12];
        float kc = 0.f;
        #pragma unroll
        for (int pp = 0; pp < 4; pp++)
            #pragma unroll
            for (int i = 0; i < 3; i++) {
                float o = rot[i*3]*kv0[pp] + rot[i*3+1]*kv1[pp] + rot[i*3+2]*kv2[pp] + t0[i];
                kp[pp * 3 + i] = o;
                kc += o * o;
            }
        *(float4*)(kh + 16) = *(float4*)(kp);
        *(float4*)(kh + 20) = *(float4*)(kp + 4);
        *(float4*)(kh + 24) = *(float4*)(kp + 8);
        g_kc[n * NHD + h] = -0.5f * hw * kc;
        float vp[24];
        #pragma unroll
        for (int pv = 0; pv < 8; pv++) {
            int pp = 4 + pv;
            #pragma unroll
            for (int i = 0; i < 3; i++)
                vp[pv * 3 + i] = rot[i*3]*kv0[pp] + rot[i*3+1]*kv1[pp] + rot[i*3+2]*kv2[pp] + t0[i];
        }
        #pragma unroll
        for (int c4 = 0; c4 < 6; c4++)
            *(float4*)(va + 16 + c4 * 4) = *(float4*)(vp + c4 * 4);
    }
}

// ---------------- qk logits (K=28 GEMM) + kc + mask per head ----------------
__global__ __launch_bounds__(256) void k_qk(const float* __restrict__ mask) {
    __shared__ __align__(16) float Qs[28][68];
    __shared__ __align__(16) float Ks[28][68];
    __shared__ float kcs[64], uli[64], ulj[64];
    int h = blockIdx.z, i0 = blockIdx.y * 64, j0 = blockIdx.x * 64;
    int t = threadIdx.x;
    for (int idx = t; idx < 64 * 28; idx += 256) {
        int m = idx / 28, k = idx % 28;
        Qs[k][m] = g_qhat[(size_t)(i0 + m) * 384 + h * 32 + k];
        Ks[k][m] = g_khat[(size_t)(j0 + m) * 384 + h * 32 + k];
    }
    if (t < 64) {
        kcs[t] = g_kc[(j0 + t) * NHD + h];
        uli[t] = mask[(i0 + t) * 5];
        ulj[t] = mask[(j0 + t) * 5];
    }
    __syncthreads();
    int tx = t & 15, ty = t >> 4;
    u64 acc2[4][2] = {};
    #pragma unroll
    for (int k = 0; k < 28; k++) {
        float4 av = *(const float4*)(&Qs[k][ty * 4]);
        ulonglong2 wv = *(const ulonglong2*)(&Ks[k][tx * 4]);
        u64 a0 = dup2(av.x), a1 = dup2(av.y), a2 = dup2(av.z), a3 = dup2(av.w);
        ffma2(acc2[0][0], a0, wv.x); ffma2(acc2[0][1], a0, wv.y);
        ffma2(acc2[1][0], a1, wv.x); ffma2(acc2[1][1], a1, wv.y);
        ffma2(acc2[2][0], a2, wv.x); ffma2(acc2[2][1], a2, wv.y);
        ffma2(acc2[3][0], a3, wv.x); ffma2(acc2[3][1], a3, wv.y);
    }
    int jb = tx * 4;
    #pragma unroll
    for (int a = 0; a < 4; a++) {
        int i = i0 + ty * 4 + a;
        float mi = uli[ty * 4 + a];
        float2 p0 = up2(acc2[a][0]), p1 = up2(acc2[a][1]);
        float4 r;
        r.x = p0.x + kcs[jb + 0] + INF_ * (mi * ulj[jb + 0] - 1.f);
        r.y = p0.y + kcs[jb + 1] + INF_ * (mi * ulj[jb + 1] - 1.f);
        r.z = p1.x + kcs[jb + 2] + INF_ * (mi * ulj[jb + 2] - 1.f);
        r.w = p1.y + kcs[jb + 3] + INF_ * (mi * ulj[jb + 3] - 1.f);
        *(float4*)(&g_logits[((size_t)i * NHD + h) * NRES + j0 + jb]) = r;
    }
}

// ---------------- persistent fused z-pass per i: bias + exp + S + o_pair ----
// 3 syncs/tile; prefetch issued right after tile-ready barrier.
#define ZT_STRIDE 132
#define ZTILE (64 * ZT_STRIDE)
#define ZAT_ES   (2 * ZTILE * 4)                 // 67584
#define ZAT_WB2  (ZAT_ES + 64 * 12 * 4)          // 70656
#define ZAT_PH   (ZAT_WB2 + 128 * 6 * 8)         // 76800
#define ZAT_SS   (ZAT_PH + 256 * 12 * 8)         // 101376
#define ZAT_SMEM (ZAT_SS + 64)                   // 101440

__global__ __launch_bounds__(256) void k_zattn(const float* __restrict__ z,
                                               const float* __restrict__ wb) {
    extern __shared__ __align__(16) unsigned char smraw[];
    float* zs  = (float*)smraw;
    float* es  = (float*)(smraw + ZAT_ES);
    u64*   wb2 = (u64*)(smraw + ZAT_WB2);
    u64*   ph  = (u64*)(smraw + ZAT_PH);
    float* Ssum= (float*)(smraw + ZAT_SS);

    int i = blockIdx.x;
    int t = threadIdx.x;
    int lane = t & 31, warp = t >> 5;
    const float c2 = 0.57735026918962576f;  // sqrt(1/3)

    for (int e = t; e < 768; e += 256) {
        int c = e / 6, p = e % 6;
        wb2[e] = pk2(c2 * wb[(2 * p) * 128 + c], c2 * wb[(2 * p + 1) * 128 + c]);
    }

    const float4* zbase = (const float4*)(z + (size_t)i * NRES * CZD);
    #pragma unroll
    for (int l = 0; l < 8; l++) {
        int idx = t + l * 256;
        cpa16(zs + (idx >> 5) * ZT_STRIDE + (idx & 31) * 4, zbase + idx);
    }
    cpa_commit();

    u64 accO[12] = {};
    float sacc[2] = {0.f, 0.f};
    int buf = 0;

    for (int jt = 0; jt < 12; jt++) {
        cpa_wait0();
        __syncthreads();   // tile jt visible; prev tile's phase-2 reads of buf^1 closed
        const float* zt = zs + buf * ZTILE;

        // prefetch next tile into buf^1 (its last readers completed before the barrier above)
        if (jt < 11) {
            float* zb = zs + (buf ^ 1) * ZTILE;
            const float4* zrow = zbase + (jt + 1) * 2048;
            #pragma unroll
            for (int l = 0; l < 8; l++) {
                int idx = t + l * 256;
                cpa16(zb + (idx >> 5) * ZT_STRIDE + (idx & 31) * 4, zrow + idx);
            }
            cpa_commit();
        }

        // phase 1: 2 j rows per thread (ja = t&31, jb = ja+32), 16-c eighth q8 = t>>5
        {
            int ja = t & 31, q8 = t >> 5;
            const float* zja = zt + ja * ZT_STRIDE + q8 * 16;
            const float* zjb = zja + 32 * ZT_STRIDE;
            u64 acc[12] = {};
            #pragma unroll
            for (int c4 = 0; c4 < 4; c4++) {
                float va[4], vb[4];
                *(float4*)va = *(const float4*)(zja + c4 * 4);
                *(float4*)vb = *(const float4*)(zjb + c4 * 4);
                int cb = (q8 * 16 + c4 * 4) * 6;
                #pragma unroll
                for (int cc = 0; cc < 4; cc++) {
                    u64 za = dup2(va[cc]), zb2 = dup2(vb[cc]);
                    ulonglong2 wA = *(const ulonglong2*)(wb2 + cb + cc * 6);
                    ulonglong2 wB = *(const ulonglong2*)(wb2 + cb + cc * 6 + 2);
                    ulonglong2 wC = *(const ulonglong2*)(wb2 + cb + cc * 6 + 4);
                    ffma2(acc[0], za, wA.x);  ffma2(acc[1], za, wA.y);
                    ffma2(acc[2], za, wB.x);  ffma2(acc[3], za, wB.y);
                    ffma2(acc[4], za, wC.x);  ffma2(acc[5], za, wC.y);
                    ffma2(acc[6], zb2, wA.x); ffma2(acc[7], zb2, wA.y);
                    ffma2(acc[8], zb2, wB.x); ffma2(acc[9], zb2, wB.y);
                    ffma2(acc[10], zb2, wC.x); ffma2(acc[11], zb2, wC.y);
                }
            }
            #pragma unroll
            for (int p = 0; p < 12; p++) ph[t * 12 + p] = acc[p];
        }
        __syncthreads();

        // combine 8 c-eighths + qk logits + exp (192 threads)
        if (t < 192) {
            int j = t & 63, pg = t >> 6;
            int j0 = jt * 64;
            int jj2 = j & 31, sub = (j >> 5) * 6;
            #pragma unroll
            for (int pp2 = 0; pp2 < 2; pp2++) {
                int p = pg * 2 + pp2;
                float sx = 0.f, sy = 0.f;
                #pragma unroll
                for (int q8 = 0; q8 < 8; q8++) {
                    float2 v = up2(ph[(q8 * 32 + jj2) * 12 + sub + p]);
                    sx += v.x; sy += v.y;
                }
                int h0 = 2 * p, h1 = 2 * p + 1;
                size_t gi0 = ((size_t)i * NHD + h0) * NRES + j0 + j;
                size_t gi1 = ((size_t)i * NHD + h1) * NRES + j0 + j;
                float e0 = __expf(g_logits[gi0] + sx);
                float e1 = __expf(g_logits[gi1] + sy);
                g_logits[gi0] = e0; g_logits[gi1] = e1;
                es[j * 12 + h0] = e0; es[j * 12 + h1] = e1;
            }
        }
        __syncthreads();

        // partial S per head
        {
            int cnt = 0;
            for (int h = warp; h < NHD; h += 8, cnt++) {
                float s = es[lane * 12 + h] + es[(lane + 32) * 12 + h];
                #pragma unroll
                for (int o = 16; o; o >>= 1) s += __shfl_xor_sync(0xffffffffu, s, o);
                sacc[cnt] += s;
            }
        }

        // phase 2: 2 c per thread (c = (t&63)*2), 16-j quarter g = t>>6
        {
            int c = (t & 63) * 2, g = t >> 6;
            #pragma unroll 4
            for (int jj = 0; jj < 16; jj++) {
                int j = g * 16 + jj;
                float2 zv = *(const float2*)(zt + j * ZT_STRIDE + c);
                u64 zd0 = dup2(zv.x), zd1 = dup2(zv.y);
                const ulonglong2* aj = (const ulonglong2*)(es + j * 12);
                ulonglong2 a0 = aj[0], a1 = aj[1], a2 = aj[2];
                ffma2(accO[0], zd0, a0.x); ffma2(accO[1], zd0, a0.y);
                ffma2(accO[2], zd0, a1.x); ffma2(accO[3], zd0, a1.y);
                ffma2(accO[4], zd0, a2.x); ffma2(accO[5], zd0, a2.y);
                ffma2(accO[6], zd1, a0.x); ffma2(accO[7], zd1, a0.y);
                ffma2(accO[8], zd1, a1.x); ffma2(accO[9], zd1, a1.y);
                ffma2(accO[10], zd1, a2.x); ffma2(accO[11], zd1, a2.y);
            }
        }
        buf ^= 1;
    }

    // finalize S
    if (lane == 0) {
        int cnt = 0;
        for (int h = warp; h < NHD; h += 8, cnt++) Ssum[h] = sacc[cnt];
    }
    __syncthreads();
    if (t < NHD) {
        float inv = 1.0f / Ssum[t];
        Ssum[t] = inv;
        g_Sinv[i * NHD + t] = inv;
    }
    __syncthreads();

    // reduce o_pair across 4 j-groups, normalize, write
    {
        u64* red = (u64*)zs;
        int cl = t & 63, g = t >> 6;
        if (g > 0) {
            u64* dst = red + ((g - 1) * 64 + cl) * 12;
            #pragma unroll
            for (int p = 0; p < 12; p++) dst[p] = accO[p];
        }
        __syncthreads();
        if (g == 0) {
            #pragma unroll
            for (int p = 0; p < 12; p++) {
                float2 a = up2(accO[p]);
                #pragma unroll
                for (int gg = 0; gg < 3; gg++) {
                    float2 b = up2(red[(gg * 64 + cl) * 12 + p]);
                    a.x += b.x; a.y += b.y;
                }
                accO[p] = pk2(a.x, a.y);
            }
            int c = cl * 2;
            float* ob = g_cat + (size_t)i * 2112 + 576;
            #pragma unroll
            for (int p = 0; p < 6; p++) {
                int h0 = 2 * p, h1 = 2 * p + 1;
                float2 vc0 = up2(accO[p]);
                float2 vc1 = up2(accO[6 + p]);
                float s0 = Ssum[h0], s1 = Ssum[h1];
                *(float2*)(ob + h0 * 128 + c) = make_float2(vc0.x * s0, vc1.x * s0);
                *(float2*)(ob + h1 * 128 + c) = make_float2(vc0.y * s1, vc1.y * s1);
            }
        }
    }
}

// ---------------- o = (e@v)/S, o_pt = inv-frame((e@v_pts)/S) fused ----------
#define OV_AT   0                       // a_t [64 k][36]: 9216
#define OV_VS   9216                    // v_s [64 k][40]: 10240
#define OV_RED  19456                   // red 2*32*20 u64: 10240
#define OV_OPT  29696                   // opts [32][24]: 3072
#define OV_SMEM 32768

__global__ __launch_bounds__(128) void k_ov(const float* __restrict__ r_rot,
                                            const float* __restrict__ r_trans) {
    extern __shared__ __align__(16) unsigned char sm[];
    float* a_t  = (float*)(sm + OV_AT);
    float* v_s  = (float*)(sm + OV_VS);
    u64*   red  = (u64*)(sm + OV_RED);
    float* opts = (float*)(sm + OV_OPT);
    int i0 = blockIdx.x * 32;
    int h  = blockIdx.y;
    int t  = threadIdx.x;
    int rq = t & 7, cq = (t >> 3) & 3, ks = t >> 5;
    u64 acc[4][5] = {};
    for (int jt = 0; jt < 12; jt++) {
        #pragma unroll
        for (int l = 0; l < 16; l++) {
            int idx = t + l * 128;
            int r = idx >> 6, k = idx & 63;
            a_t[k * 36 + r] = g_logits[((size_t)(i0 + r) * NHD + h) * NRES + jt * 64 + k];
        }
        #pragma unroll
        for (int l = 0; l < 20; l++) {
            int idx = t + l * 128;
            v_s[idx] = g_vall[((size_t)(jt * 64 + idx / 40) * NHD + h) * 40 + idx % 40];
        }
        __syncthreads();
        #pragma unroll
        for (int kk = 0; kk < 16; kk++) {
            int k = ks * 16 + kk;
            float4 av = *(const float4*)(a_t + k * 36 + rq * 4);
            const u64* vv = (const u64*)(v_s + k * 40 + cq * 10);
            u64 v0 = vv[0], v1 = vv[1], v2 = vv[2], v3 = vv[3], v4 = vv[4];
            u64 a0 = dup2(av.x), a1 = dup2(av.y), a2 = dup2(av.z), a3 = dup2(av.w);
            ffma2(acc[0][0], a0, v0); ffma2(acc[0][1], a0, v1); ffma2(acc[0][2], a0, v2);
            ffma2(acc[0][3], a0, v3); ffma2(acc[0][4], a0, v4);
            ffma2(acc[1][0], a1, v0); ffma2(acc[1][1], a1, v1); ffma2(acc[1][2], a1, v2);
            ffma2(acc[1][3], a1, v3); ffma2(acc[1][4], a1, v4);
            ffma2(acc[2][0], a2, v0); ffma2(acc[2][1], a2, v1); ffma2(acc[2][2], a2, v2);
            ffma2(acc[2][3], a2, v3); ffma2(acc[2][4], a2, v4);
            ffma2(acc[3][0], a3, v0); ffma2(acc[3][1], a3, v1); ffma2(acc[3][2], a3, v2);
            ffma2(acc[3][3], a3, v3); ffma2(acc[3][4], a3, v4);
        }
        __syncthreads();
    }
    int slot = t & 31;
    if (ks >= 2) {
        u64* dst = red + ((ks - 2) * 32 + slot) * 20;
        #pragma unroll
        for (int rr = 0; rr < 4; rr++)
            #pragma unroll
            for (int p = 0; p < 5; p++) dst[rr * 5 + p] = acc[rr][p];
    }
    __syncthreads();
    if (ks < 2) {
        const u64* src = red + (ks * 32 + slot) * 20;
        #pragma unroll
        for (int rr = 0; rr < 4; rr++)
            #pragma unroll
            for (int p = 0; p < 5; p++) {
                float2 a = up2(acc[rr][p]), b = up2(src[rr * 5 + p]);
                acc[rr][p] = pk2(a.x + b.x, a.y + b.y);
            }
    }
    __syncthreads();
    if (ks == 1) {
        u64* dst = red + slot * 20;
        #pragma unroll
        for (int rr = 0; rr < 4; rr++)
            #pragma unroll
            for (int p = 0; p < 5; p++) dst[rr * 5 + p] = acc[rr][p];
    }
    __syncthreads();
    if (ks == 0) {
        const u64* src = red + slot * 20;
        #pragma unroll
        for (int rr = 0; rr < 4; rr++) {
            int rl = rq * 4 + rr;
            float inv = g_Sinv[(i0 + rl) * NHD + h];
            #pragma unroll
            for (int p = 0; p < 5; p++) {
                float2 a = up2(acc[rr][p]), b = up2(src[rr * 5 + p]);
                float vx = (a.x + b.x) * inv, vy = (a.y + b.y) * inv;
                int c0 = cq * 10 + 2 * p;
                if (c0 < 16)     g_cat[(size_t)(i0 + rl) * 2112 + h * 16 + c0] = vx;
                else             opts[rl * 24 + (c0 - 16)] = vx;
                int c1 = c0 + 1;
                if (c1 < 16)     g_cat[(size_t)(i0 + rl) * 2112 + h * 16 + c1] = vy;
                else             opts[rl * 24 + (c1 - 16)] = vy;
            }
        }
    }
    __syncthreads();
    for (int e2 = t; e2 < 256; e2 += 128) {
        int rl = e2 >> 3, pv = e2 & 7;
        int n = i0 + rl;
        const float* pp = opts + rl * 24 + pv * 3;
        float d0 = pp[0] - r_trans[n * 15 + 0];
        float d1 = pp[1] - r_trans[n * 15 + 1];
        float d2 = pp[2] - r_trans[n * 15 + 2];
        const float* R = r_rot + n * 45;
        float o0 = R[0] * d0 + R[3] * d1 + R[6] * d2;
        float o1 = R[1] * d0 + R[4] * d1 + R[7] * d2;
        float o2 = R[2] * d0 + R[5] * d1 + R[8] * d2;
        float nm = sqrtf(o0 * o0 + o1 * o1 + o2 * o2 + 1e-8f);
        float* cb = g_cat + (size_t)n * 2112 + 192;
        int rr2 = h * 8 + pv;
        cb[rr2] = o0; cb[96 + rr2] = o1; cb[192 + rr2] = o2; cb[288 + rr2] = nm;
    }
}

// ---------------- launch ----------------
extern "C" void kernel_launch(void* const* d_in, const int* in_sizes, int n_in,
                              void* d_out, int out_size) {
    const float* s       = (const float*)d_in[0];
    const float* z       = (const float*)d_in[1];
    const float* r_rot   = (const float*)d_in[2];
    const float* r_trans = (const float*)d_in[3];
    const float* mask    = (const float*)d_in[4];
    const float* wq      = (const float*)d_in[5];
    const float* bq      = (const float*)d_in[6];
    const float* wkv     = (const float*)d_in[7];
    const float* bkv     = (const float*)d_in[8];
    const float* wqp     = (const float*)d_in[9];
    const float* bqp     = (const float*)d_in[10];
    const float* wkvp    = (const float*)d_in[11];
    const float* bkvp    = (const float*)d_in[12];
    const float* wb      = (const float*)d_in[13];
    const float* head_w  = (const float*)d_in[15];
    const float* wout    = (const float*)d_in[16];
    const float* bout    = (const float*)d_in[17];
    const float* wexp    = (const float*)d_in[18];
    const float* bexp    = (const float*)d_in[19];
    const float* ln_g    = (const float*)d_in[20];
    const float* ln_b    = (const float*)d_in[21];
    float* out = (float*)d_out;

    float *p_cat = nullptr, *p_part = nullptr;
    cudaGetSymbolAddress((void**)&p_cat,  g_cat);
    cudaGetSymbolAddress((void**)&p_part, g_part);

    static int attn_cfg = 0;
    if (!attn_cfg) {
        cudaFuncSetAttribute(k_zattn, cudaFuncAttributeMaxDynamicSharedMemorySize, ZAT_SMEM);
        cudaFuncSetAttribute(k_ov, cudaFuncAttributeMaxDynamicSharedMemorySize, OV_SMEM);
        attn_cfg = 1;
    }

    k_gemm64<<<dim3(6, 12, 2), 256>>>(s, wexp, nullptr, p_part, 384, 384, 12, 0, NRES * CSD);
    k_ln<<<768, 128>>>(bexp, ln_g, ln_b);
    k_gemm_proj<<<dim3(18, 12), 256>>>(wq, bq, wkv, bkv, wqp, bqp, wkvp, bkvp);
    k_assemble<<<96, 256>>>(r_rot, r_trans, head_w);
    k_qk<<<dim3(12, 12, 12), 256>>>(mask);
    k_zattn<<<768, 256, ZAT_SMEM>>>(z, wb);
    k_ov<<<dim3(24, 12), 128, OV_SMEM>>>(r_rot, r_trans);
    k_gemm64<<<dim3(6, 12, 4), 256>>>(p_cat, wout, nullptr, p_part, 2112, 384, 33, 0, NRES * CSD);
    k_combine<<<1152, 256>>>(bout, out);
}

// round 17
// speedup vs baseline: 1.0577x; 1.0577x over previous
#include <cuda_runtime.h>
#include <math.h>

#define NRES 768
#define CSD  384
#define CZD  128
#define NHD  12
#define INF_ 100000.0f

typedef unsigned long long u64;

// ---------------- packed f32x2 helpers ----------------
__device__ __forceinline__ void ffma2(u64& d, u64 a, u64 b) {
    asm("fma.rn.f32x2 %0, %1, %2, %0;" : "+l"(d) : "l"(a), "l"(b));
}
__device__ __forceinline__ u64 dup2(float x) {
    u64 r; asm("mov.b64 %0, {%1, %1};" : "=l"(r) : "f"(x)); return r;
}
__device__ __forceinline__ u64 pk2(float lo, float hi) {
    u64 r; asm("mov.b64 %0, {%1, %2};" : "=l"(r) : "f"(lo), "f"(hi)); return r;
}
__device__ __forceinline__ float2 up2(u64 v) {
    float lo, hi; asm("mov.b64 {%0, %1}, %2;" : "=f"(lo), "=f"(hi) : "l"(v));
    return make_float2(lo, hi);
}
// ---------------- cp.async helpers ----------------
__device__ __forceinline__ void cpa16(void* dst, const void* src) {
    unsigned sdst = (unsigned)__cvta_generic_to_shared(dst);
    asm volatile("cp.async.cg.shared.global [%0], [%1], 16;" :: "r"(sdst), "l"(src));
}
__device__ __forceinline__ void cpa_commit() { asm volatile("cp.async.commit_group;"); }
__device__ __forceinline__ void cpa_wait1() { asm volatile("cp.async.wait_group 1;"); }
__device__ __forceinline__ void cpa_wait0() { asm volatile("cp.async.wait_group 0;"); }

// ---------------- scratch (device globals; no allocation) ----------------
__device__ float g_se[NRES * CSD];
__device__ float g_proj[NRES * 1152];
__device__ float g_qhat[NRES * 384];          // per n: 12 heads x 32 (28 used)
__device__ float g_khat[NRES * 384];
__device__ float g_kc[NRES * NHD];
__device__ float g_vall[NRES * NHD * 40];
__device__ float g_cat[NRES * 2112];
__device__ float g_part[4][NRES * CSD];
__device__ float g_logits[NHD * NRES * NRES]; // [i][h][j]: qk-logits, then unnormalized exp
__device__ float g_Sinv[NRES * NHD];          // 1/S per (i,h)

// =====================================================================
// fp32 GEMM with FFMA2: C = A(MxK) @ W(NxK)^T [+ bias]; 64x64 tile, BK=16.
// =====================================================================
__device__ __forceinline__ void mm16(const float* Ab, const float* Wb,
                                     int ty, int tx, u64 acc2[4][2]) {
    #pragma unroll
    for (int k = 0; k < 16; k++) {
        float4 av = *(const float4*)(Ab + k * 68 + ty * 4);
        ulonglong2 wv = *(const ulonglong2*)(Wb + k * 68 + tx * 4);
        u64 a0 = dup2(av.x), a1 = dup2(av.y), a2 = dup2(av.z), a3 = dup2(av.w);
        ffma2(acc2[0][0], a0, wv.x); ffma2(acc2[0][1], a0, wv.y);
        ffma2(acc2[1][0], a1, wv.x); ffma2(acc2[1][1], a1, wv.y);
        ffma2(acc2[2][0], a2, wv.x); ffma2(acc2[2][1], a2, wv.y);
        ffma2(acc2[3][0], a3, wv.x); ffma2(acc2[3][1], a3, wv.y);
    }
}

__global__ __launch_bounds__(256) void k_gemm64(
    const float* __restrict__ A, const float* __restrict__ W,
    const float* __restrict__ bias, float* __restrict__ C,
    int ld, int ldc, int nkt, int add_bias, int partStride)
{
    __shared__ __align__(16) float As[2][16][68];
    __shared__ __align__(16) float Ws[2][16][68];
    int t  = threadIdx.x;
    int m0 = blockIdx.y * 64, n0 = blockIdx.x * 64;
    int kt0 = blockIdx.z * nkt;
    C += (size_t)blockIdx.z * partStride;
    int lr = t >> 2, lk = (t & 3) * 4;
    const float* arow = A + (size_t)(m0 + lr) * ld + kt0 * 16 + lk;
    const float* wrow = W + (size_t)(n0 + lr) * ld + kt0 * 16 + lk;
    int tx = t & 15, ty = t >> 4;

    u64 acc2[4][2] = {};
    float4 ra = *(const float4*)arow;
    float4 rw = *(const float4*)wrow;
    int buf = 0;
    As[0][lk+0][lr]=ra.x; As[0][lk+1][lr]=ra.y; As[0][lk+2][lr]=ra.z; As[0][lk+3][lr]=ra.w;
    Ws[0][lk+0][lr]=rw.x; Ws[0][lk+1][lr]=rw.y; Ws[0][lk+2][lr]=rw.z; Ws[0][lk+3][lr]=rw.w;

    for (int kt = 0; kt < nkt - 1; kt++) {
        __syncthreads();
        ra = *(const float4*)(arow + (kt + 1) * 16);
        rw = *(const float4*)(wrow + (kt + 1) * 16);
        mm16(&As[buf][0][0], &Ws[buf][0][0], ty, tx, acc2);
        int nb = buf ^ 1;
        As[nb][lk+0][lr]=ra.x; As[nb][lk+1][lr]=ra.y; As[nb][lk+2][lr]=ra.z; As[nb][lk+3][lr]=ra.w;
        Ws[nb][lk+0][lr]=rw.x; Ws[nb][lk+1][lr]=rw.y; Ws[nb][lk+2][lr]=rw.z; Ws[nb][lk+3][lr]=rw.w;
        buf = nb;
    }
    __syncthreads();
    mm16(&As[buf][0][0], &Ws[buf][0][0], ty, tx, acc2);

    float4 bv = make_float4(0.f, 0.f, 0.f, 0.f);
    if (add_bias) bv = *(const float4*)(bias + n0 + tx * 4);
    #pragma unroll
    for (int a = 0; a < 4; a++) {
        float2 p0 = up2(acc2[a][0]), p1 = up2(acc2[a][1]);
        float4 r = make_float4(p0.x + bv.x, p0.y + bv.y, p1.x + bv.z, p1.y + bv.w);
        *(float4*)(C + (size_t)(m0 + ty * 4 + a) * ldc + n0 + tx * 4) = r;
    }
}

__device__ __forceinline__ float proj_bias(int n, const float* bq, const float* bkv,
                                           const float* bqp, const float* bkvp) {
    if (n < 192) return bq[n];
    if (n < 576) return bkv[n - 192];
    if (n < 720) return bqp[n - 576];
    return bkvp[n - 720];
}

__global__ __launch_bounds__(256) void k_gemm_proj(
    const float* __restrict__ wq,  const float* __restrict__ bq,
    const float* __restrict__ wkv, const float* __restrict__ bkv,
    const float* __restrict__ wqp, const float* __restrict__ bqp,
    const float* __restrict__ wkvp,const float* __restrict__ bkvp)
{
    __shared__ __align__(16) float As[2][16][68];
    __shared__ __align__(16) float Ws[2][16][68];
    int t  = threadIdx.x;
    int m0 = blockIdx.y * 64, n0 = blockIdx.x * 64;
    int lr = t >> 2, lk = (t & 3) * 4;
    const float* arow = g_se + (size_t)(m0 + lr) * 384 + lk;
    int n = n0 + lr;
    const float* wbase; int nl;
    if      (n < 192) { wbase = wq;   nl = n; }
    else if (n < 576) { wbase = wkv;  nl = n - 192; }
    else if (n < 720) { wbase = wqp;  nl = n - 576; }
    else              { wbase = wkvp; nl = n - 720; }
    const float* wrow = wbase + (size_t)nl * 384 + lk;
    int tx = t & 15, ty = t >> 4;

    u64 acc2[4][2] = {};
    float4 ra = *(const float4*)arow;
    float4 rw = *(const float4*)wrow;
    int buf = 0;
    As[0][lk+0][lr]=ra.x; As[0][lk+1][lr]=ra.y; As[0][lk+2][lr]=ra.z; As[0][lk+3][lr]=ra.w;
    Ws[0][lk+0][lr]=rw.x; Ws[0][lk+1][lr]=rw.y; Ws[0][lk+2][lr]=rw.z; Ws[0][lk+3][lr]=rw.w;

    const int nkt = 24;
    for (int kt = 0; kt < nkt - 1; kt++) {
        __syncthreads();
        ra = *(const float4*)(arow + (kt + 1) * 16);
        rw = *(const float4*)(wrow + (kt + 1) * 16);
        mm16(&As[buf][0][0], &Ws[buf][0][0], ty, tx, acc2);
        int nb = buf ^ 1;
        As[nb][lk+0][lr]=ra.x; As[nb][lk+1][lr]=ra.y; As[nb][lk+2][lr]=ra.z; As[nb][lk+3][lr]=ra.w;
        Ws[nb][lk+0][lr]=rw.x; Ws[nb][lk+1][lr]=rw.y; Ws[nb][lk+2][lr]=rw.z; Ws[nb][lk+3][lr]=rw.w;
        buf = nb;
    }
    __syncthreads();
    mm16(&As[buf][0][0], &Ws[buf][0][0], ty, tx, acc2);

    int nc = n0 + tx * 4;
    float4 bv = make_float4(proj_bias(nc + 0, bq, bkv, bqp, bkvp),
                            proj_bias(nc + 1, bq, bkv, bqp, bkvp),
                            proj_bias(nc + 2, bq, bkv, bqp, bkvp),
                            proj_bias(nc + 3, bq, bkv, bqp, bkvp));
    #pragma unroll
    for (int a = 0; a < 4; a++) {
        float2 p0 = up2(acc2[a][0]), p1 = up2(acc2[a][1]);
        float4 r = make_float4(p0.x + bv.x, p0.y + bv.y, p1.x + bv.z, p1.y + bv.w);
        *(float4*)(g_proj + (size_t)(m0 + ty * 4 + a) * 1152 + nc) = r;
    }
}

__global__ void k_combine(const float* __restrict__ bout, float* __restrict__ out) {
    int i = blockIdx.x * 256 + threadIdx.x;
    out[i] = g_part[0][i] + g_part[1][i] + g_part[2][i] + g_part[3][i] + bout[i % 384];
}

// ---------------- LayerNorm over split-K partials ----------------
__global__ void k_ln(const float* __restrict__ bexp,
                     const float* __restrict__ gamma, const float* __restrict__ beta) {
    int n = blockIdx.x, t = threadIdx.x;
    const float* P0 = g_part[0] + (size_t)n * CSD;
    const float* P1 = g_part[1] + (size_t)n * CSD;
    float x0 = P0[t]       + P1[t]       + bexp[t];
    float x1 = P0[t + 128] + P1[t + 128] + bexp[t + 128];
    float x2 = P0[t + 256] + P1[t + 256] + bexp[t + 256];
    float s1 = x0 + x1 + x2;
    float s2 = x0 * x0 + x1 * x1 + x2 * x2;
    __shared__ float r1[4], r2[4];
    #pragma unroll
    for (int o = 16; o; o >>= 1) {
        s1 += __shfl_xor_sync(0xffffffffu, s1, o);
        s2 += __shfl_xor_sync(0xffffffffu, s2, o);
    }
    if ((t & 31) == 0) { r1[t >> 5] = s1; r2[t >> 5] = s2; }
    __syncthreads();
    float ts1 = r1[0] + r1[1] + r1[2] + r1[3];
    float ts2 = r2[0] + r2[1] + r2[2] + r2[3];
    float mu  = ts1 * (1.f / 384.f);
    float var = ts2 * (1.f / 384.f) - mu * mu;
    float inv = rsqrtf(var + 1e-5f);
    float* row = g_se + (size_t)n * CSD;
    row[t]       = (x0 - mu) * inv * gamma[t]       + beta[t];
    row[t + 128] = (x1 - mu) * inv * gamma[t + 128] + beta[t + 128];
    row[t + 256] = (x2 - mu) * inv * gamma[t + 256] + beta[t + 256];
}

// ---------------- assemble (vectorized LDG.128/STG.128) ----------------
__global__ void k_assemble(const float* __restrict__ r_rot, const float* __restrict__ r_trans,
                           const float* __restrict__ head_w) {
    int gw   = blockIdx.x * 8 + (threadIdx.x >> 5);
    int lane = threadIdx.x & 31;
    if (gw >= NRES || lane >= NHD) return;
    int n = gw, h = lane;
    float rot[9], t0[3];
    #pragma unroll
    for (int i = 0; i < 9; i++) rot[i] = r_rot[n * 45 + i];
    #pragma unroll
    for (int i = 0; i < 3; i++) t0[i] = r_trans[n * 15 + i];
    float hw = log1pf(expf(head_w[h])) * rsqrtf(54.0f);
    const float c1 = rsqrtf(48.0f);
    const float* P = g_proj + (size_t)n * 1152;
    float* qh = g_qhat + (size_t)n * 384 + h * 32;
    float* kh = g_khat + (size_t)n * 384 + h * 32;
    float* va = g_vall + ((size_t)n * NHD + h) * 40;
    #pragma unroll
    for (int c4 = 0; c4 < 4; c4++) {
        float4 q = *(const float4*)(P + h * 16 + c4 * 4);
        q.x *= c1; q.y *= c1; q.z *= c1; q.w *= c1;
        *(float4*)(qh + c4 * 4) = q;
        *(float4*)(kh + c4 * 4) = *(const float4*)(P + 192 + h * 32 + c4 * 4);
        *(float4*)(va + c4 * 4) = *(const float4*)(P + 192 + h * 32 + 16 + c4 * 4);
    }
    {
        float4 l0 = *(const float4*)(P + 576 + h * 4);
        float4 l1 = *(const float4*)(P + 576 + 48 + h * 4);
        float4 l2 = *(const float4*)(P + 576 + 96 + h * 4);
        float a0[4] = {l0.x, l0.y, l0.z, l0.w};
        float a1[4] = {l1.x, l1.y, l1.z, l1.w};
        float a2[4] = {l2.x, l2.y, l2.z, l2.w};
        float qp[12];
        #pragma unroll
        for (int pp = 0; pp < 4; pp++)
            #pragma unroll
            for (int i = 0; i < 3; i++)
                qp[pp * 3 + i] = hw * (rot[i*3]*a0[pp] + rot[i*3+1]*a1[pp] + rot[i*3+2]*a2[pp] + t0[i]);
        *(float4*)(qh + 16) = *(float4*)(qp);
        *(float4*)(qh + 20) = *(float4*)(qp + 4);
        *(float4*)(qh + 24) = *(float4*)(qp + 8);
    }
    {
        float kv0[12], kv1[12], kv2[12];
        #pragma unroll
        for (int c4 = 0; c4 < 3; c4++) {
            *(float4*)(kv0 + c4 * 4) = *(const float4*)(P + 720 +   0 + h * 12 + c4 * 4);
            *(float4*)(kv1 + c4 * 4) = *(const float4*)(P + 720 + 144 + h * 12 + c4 * 4);
            *(float4*)(kv2 + c4 * 4) = *(const float4*)(P + 720 + 288 + h * 12 + c4 * 4);
        }
        float kp[12];
        float kc = 0.f;
        #pragma unroll
        for (int pp = 0; pp < 4; pp++)
            #pragma unroll
            for (int i = 0; i < 3; i++) {
                float o = rot[i*3]*kv0[pp] + rot[i*3+1]*kv1[pp] + rot[i*3+2]*kv2[pp] + t0[i];
                kp[pp * 3 + i] = o;
                kc += o * o;
            }
        *(float4*)(kh + 16) = *(float4*)(kp);
        *(float4*)(kh + 20) = *(float4*)(kp + 4);
        *(float4*)(kh + 24) = *(float4*)(kp + 8);
        g_kc[n * NHD + h] = -0.5f * hw * kc;
        float vp[24];
        #pragma unroll
        for (int pv = 0; pv < 8; pv++) {
            int pp = 4 + pv;
            #pragma unroll
            for (int i = 0; i < 3; i++)
                vp[pv * 3 + i] = rot[i*3]*kv0[pp] + rot[i*3+1]*kv1[pp] + rot[i*3+2]*kv2[pp] + t0[i];
        }
        #pragma unroll
        for (int c4 = 0; c4 < 6; c4++)
            *(float4*)(va + 16 + c4 * 4) = *(float4*)(vp + c4 * 4);
    }
}

// ---------------- qk logits (K=28 GEMM) + kc + mask per head ----------------
__global__ __launch_bounds__(256) void k_qk(const float* __restrict__ mask) {
    __shared__ __align__(16) float Qs[28][68];
    __shared__ __align__(16) float Ks[28][68];
    __shared__ float kcs[64], uli[64], ulj[64];
    int h = blockIdx.z, i0 = blockIdx.y * 64, j0 = blockIdx.x * 64;
    int t = threadIdx.x;
    for (int idx = t; idx < 64 * 28; idx += 256) {
        int m = idx / 28, k = idx % 28;
        Qs[k][m] = g_qhat[(size_t)(i0 + m) * 384 + h * 32 + k];
        Ks[k][m] = g_khat[(size_t)(j0 + m) * 384 + h * 32 + k];
    }
    if (t < 64) {
        kcs[t] = g_kc[(j0 + t) * NHD + h];
        uli[t] = mask[(i0 + t) * 5];
        ulj[t] = mask[(j0 + t) * 5];
    }
    __syncthreads();
    int tx = t & 15, ty = t >> 4;
    u64 acc2[4][2] = {};
    #pragma unroll
    for (int k = 0; k < 28; k++) {
        float4 av = *(const float4*)(&Qs[k][ty * 4]);
        ulonglong2 wv = *(const ulonglong2*)(&Ks[k][tx * 4]);
        u64 a0 = dup2(av.x), a1 = dup2(av.y), a2 = dup2(av.z), a3 = dup2(av.w);
        ffma2(acc2[0][0], a0, wv.x); ffma2(acc2[0][1], a0, wv.y);
        ffma2(acc2[1][0], a1, wv.x); ffma2(acc2[1][1], a1, wv.y);
        ffma2(acc2[2][0], a2, wv.x); ffma2(acc2[2][1], a2, wv.y);
        ffma2(acc2[3][0], a3, wv.x); ffma2(acc2[3][1], a3, wv.y);
    }
    int jb = tx * 4;
    #pragma unroll
    for (int a = 0; a < 4; a++) {
        int i = i0 + ty * 4 + a;
        float mi = uli[ty * 4 + a];
        float2 p0 = up2(acc2[a][0]), p1 = up2(acc2[a][1]);
        float4 r;
        r.x = p0.x + kcs[jb + 0] + INF_ * (mi * ulj[jb + 0] - 1.f);
        r.y = p0.y + kcs[jb + 1] + INF_ * (mi * ulj[jb + 1] - 1.f);
        r.z = p1.x + kcs[jb + 2] + INF_ * (mi * ulj[jb + 2] - 1.f);
        r.w = p1.y + kcs[jb + 3] + INF_ * (mi * ulj[jb + 3] - 1.f);
        *(float4*)(&g_logits[((size_t)i * NHD + h) * NRES + j0 + jb]) = r;
    }
}

// ---------------- persistent fused z-pass per i (R15 structure) ----------
#define ZT_STRIDE 132
#define ZTILE (64 * ZT_STRIDE)
#define ZAT_ES   (2 * ZTILE * 4)                 // 67584
#define ZAT_WB2  (ZAT_ES + 64 * 12 * 4)          // 70656
#define ZAT_PH   (ZAT_WB2 + 128 * 6 * 8)         // 76800
#define ZAT_SS   (ZAT_PH + 256 * 12 * 8)         // 101376
#define ZAT_SMEM (ZAT_SS + 64)                   // 101440

__global__ __launch_bounds__(256) void k_zattn(const float* __restrict__ z,
                                               const float* __restrict__ wb) {
    extern __shared__ __align__(16) unsigned char smraw[];
    float* zs  = (float*)smraw;
    float* es  = (float*)(smraw + ZAT_ES);
    u64*   wb2 = (u64*)(smraw + ZAT_WB2);
    u64*   ph  = (u64*)(smraw + ZAT_PH);
    float* Ssum= (float*)(smraw + ZAT_SS);

    int i = blockIdx.x;
    int t = threadIdx.x;
    int lane = t & 31, warp = t >> 5;
    const float c2 = 0.57735026918962576f;  // sqrt(1/3)

    for (int e = t; e < 768; e += 256) {
        int c = e / 6, p = e % 6;
        wb2[e] = pk2(c2 * wb[(2 * p) * 128 + c], c2 * wb[(2 * p + 1) * 128 + c]);
    }

    const float4* zbase = (const float4*)(z + (size_t)i * NRES * CZD);
    #pragma unroll
    for (int l = 0; l < 8; l++) {
        int idx = t + l * 256;
        cpa16(zs + (idx >> 5) * ZT_STRIDE + (idx & 31) * 4, zbase + idx);
    }
    cpa_commit();

    u64 accO[12] = {};
    float sacc[2] = {0.f, 0.f};
    int buf = 0;

    for (int jt = 0; jt < 12; jt++) {
        __syncthreads();   // closes previous tile's phase-2 reads of buf^1
        if (jt < 11) {
            float* zb = zs + (buf ^ 1) * ZTILE;
            const float4* zrow = zbase + (jt + 1) * 2048;
            #pragma unroll
            for (int l = 0; l < 8; l++) {
                int idx = t + l * 256;
                cpa16(zb + (idx >> 5) * ZT_STRIDE + (idx & 31) * 4, zrow + idx);
            }
            cpa_commit();
            cpa_wait1();
        } else {
            cpa_wait0();
        }
        __syncthreads();
        const float* zt = zs + buf * ZTILE;

        // phase 1: 2 j rows per thread (ja = t&31, jb = ja+32), 16-c eighth q8 = t>>5
        {
            int ja = t & 31, q8 = t >> 5;
            const float* zja = zt + ja * ZT_STRIDE + q8 * 16;
            const float* zjb = zja + 32 * ZT_STRIDE;
            u64 acc[12] = {};
            #pragma unroll
            for (int c4 = 0; c4 < 4; c4++) {
                float va[4], vb[4];
                *(float4*)va = *(const float4*)(zja + c4 * 4);
                *(float4*)vb = *(const float4*)(zjb + c4 * 4);
                int cb = (q8 * 16 + c4 * 4) * 6;
                #pragma unroll
                for (int cc = 0; cc < 4; cc++) {
                    u64 za = dup2(va[cc]), zb2 = dup2(vb[cc]);
                    ulonglong2 wA = *(const ulonglong2*)(wb2 + cb + cc * 6);
                    ulonglong2 wB = *(const ulonglong2*)(wb2 + cb + cc * 6 + 2);
                    ulonglong2 wC = *(const ulonglong2*)(wb2 + cb + cc * 6 + 4);
                    ffma2(acc[0], za, wA.x);  ffma2(acc[1], za, wA.y);
                    ffma2(acc[2], za, wB.x);  ffma2(acc[3], za, wB.y);
                    ffma2(acc[4], za, wC.x);  ffma2(acc[5], za, wC.y);
                    ffma2(acc[6], zb2, wA.x); ffma2(acc[7], zb2, wA.y);
                    ffma2(acc[8], zb2, wB.x); ffma2(acc[9], zb2, wB.y);
                    ffma2(acc[10], zb2, wC.x); ffma2(acc[11], zb2, wC.y);
                }
            }
            #pragma unroll
            for (int p = 0; p < 12; p++) ph[t * 12 + p] = acc[p];
        }
        __syncthreads();

        // combine 8 c-eighths + qk logits + exp (192 threads)
        if (t < 192) {
            int j = t & 63, pg = t >> 6;
            int j0 = jt * 64;
            int jj2 = j & 31, sub = (j >> 5) * 6;
            #pragma unroll
            for (int pp2 = 0; pp2 < 2; pp2++) {
                int p = pg * 2 + pp2;
                float sx = 0.f, sy = 0.f;
                #pragma unroll
                for (int q8 = 0; q8 < 8; q8++) {
                    float2 v = up2(ph[(q8 * 32 + jj2) * 12 + sub + p]);
                    sx += v.x; sy += v.y;
                }
                int h0 = 2 * p, h1 = 2 * p + 1;
                size_t gi0 = ((size_t)i * NHD + h0) * NRES + j0 + j;
                size_t gi1 = ((size_t)i * NHD + h1) * NRES + j0 + j;
                float e0 = __expf(g_logits[gi0] + sx);
                float e1 = __expf(g_logits[gi1] + sy);
                g_logits[gi0] = e0; g_logits[gi1] = e1;
                es[j * 12 + h0] = e0; es[j * 12 + h1] = e1;
            }
        }
        __syncthreads();

        // partial S per head
        {
            int cnt = 0;
            for (int h = warp; h < NHD; h += 8, cnt++) {
                float s = es[lane * 12 + h] + es[(lane + 32) * 12 + h];
                #pragma unroll
                for (int o = 16; o; o >>= 1) s += __shfl_xor_sync(0xffffffffu, s, o);
                sacc[cnt] += s;
            }
        }

        // phase 2: 2 c per thread (c = (t&63)*2), 16-j quarter g = t>>6
        {
            int c = (t & 63) * 2, g = t >> 6;
            #pragma unroll 4
            for (int jj = 0; jj < 16; jj++) {
                int j = g * 16 + jj;
                float2 zv = *(const float2*)(zt + j * ZT_STRIDE + c);
                u64 zd0 = dup2(zv.x), zd1 = dup2(zv.y);
                const ulonglong2* aj = (const ulonglong2*)(es + j * 12);
                ulonglong2 a0 = aj[0], a1 = aj[1], a2 = aj[2];
                ffma2(accO[0], zd0, a0.x); ffma2(accO[1], zd0, a0.y);
                ffma2(accO[2], zd0, a1.x); ffma2(accO[3], zd0, a1.y);
                ffma2(accO[4], zd0, a2.x); ffma2(accO[5], zd0, a2.y);
                ffma2(accO[6], zd1, a0.x); ffma2(accO[7], zd1, a0.y);
                ffma2(accO[8], zd1, a1.x); ffma2(accO[9], zd1, a1.y);
                ffma2(accO[10], zd1, a2.x); ffma2(accO[11], zd1, a2.y);
            }
        }
        buf ^= 1;
    }

    // finalize S
    if (lane == 0) {
        int cnt = 0;
        for (int h = warp; h < NHD; h += 8, cnt++) Ssum[h] = sacc[cnt];
    }
    __syncthreads();
    if (t < NHD) {
        float inv = 1.0f / Ssum[t];
        Ssum[t] = inv;
        g_Sinv[i * NHD + t] = inv;
    }
    __syncthreads();

    // reduce o_pair across 4 j-groups, normalize, write
    {
        u64* red = (u64*)zs;
        int cl = t & 63, g = t >> 6;
        if (g > 0) {
            u64* dst = red + ((g - 1) * 64 + cl) * 12;
            #pragma unroll
            for (int p = 0; p < 12; p++) dst[p] = accO[p];
        }
        __syncthreads();
        if (g == 0) {
            #pragma unroll
            for (int p = 0; p < 12; p++) {
                float2 a = up2(accO[p]);
                #pragma unroll
                for (int gg = 0; gg < 3; gg++) {
                    float2 b = up2(red[(gg * 64 + cl) * 12 + p]);
                    a.x += b.x; a.y += b.y;
                }
                accO[p] = pk2(a.x, a.y);
            }
            int c = cl * 2;
            float* ob = g_cat + (size_t)i * 2112 + 576;
            #pragma unroll
            for (int p = 0; p < 6; p++) {
                int h0 = 2 * p, h1 = 2 * p + 1;
                float2 vc0 = up2(accO[p]);
                float2 vc1 = up2(accO[6 + p]);
                float s0 = Ssum[h0], s1 = Ssum[h1];
                *(float2*)(ob + h0 * 128 + c) = make_float2(vc0.x * s0, vc1.x * s0);
                *(float2*)(ob + h1 * 128 + c) = make_float2(vc0.y * s1, vc1.y * s1);
            }
        }
    }
}

// ---------------- o = (e@v)/S, o_pt = inv-frame((e@v_pts)/S) fused ----------
#define OV_AT   0                       // a_t [64 k][36]: 9216
#define OV_VS   9216                    // v_s [64 k][40]: 10240
#define OV_RED  19456                   // red 2*32*20 u64: 10240
#define OV_OPT  29696                   // opts [32][24]: 3072
#define OV_SMEM 32768

__global__ __launch_bounds__(128) void k_ov(const float* __restrict__ r_rot,
                                            const float* __restrict__ r_trans) {
    extern __shared__ __align__(16) unsigned char sm[];
    float* a_t  = (float*)(sm + OV_AT);
    float* v_s  = (float*)(sm + OV_VS);
    u64*   red  = (u64*)(sm + OV_RED);
    float* opts = (float*)(sm + OV_OPT);
    int i0 = blockIdx.x * 32;
    int h  = blockIdx.y;
    int t  = threadIdx.x;
    int rq = t & 7, cq = (t >> 3) & 3, ks = t >> 5;
    u64 acc[4][5] = {};
    for (int jt = 0; jt < 12; jt++) {
        #pragma unroll
        for (int l = 0; l < 16; l++) {
            int idx = t + l * 128;
            int r = idx >> 6, k = idx & 63;
            a_t[k * 36 + r] = g_logits[((size_t)(i0 + r) * NHD + h) * NRES + jt * 64 + k];
        }
        #pragma unroll
        for (int l = 0; l < 20; l++) {
            int idx = t + l * 128;
            v_s[idx] = g_vall[((size_t)(jt * 64 + idx / 40) * NHD + h) * 40 + idx % 40];
        }
        __syncthreads();
        #pragma unroll
        for (int kk = 0; kk < 16; kk++) {
            int k = ks * 16 + kk;
            float4 av = *(const float4*)(a_t + k * 36 + rq * 4);
            const u64* vv = (const u64*)(v_s + k * 40 + cq * 10);
            u64 v0 = vv[0], v1 = vv[1], v2 = vv[2], v3 = vv[3], v4 = vv[4];
            u64 a0 = dup2(av.x), a1 = dup2(av.y), a2 = dup2(av.z), a3 = dup2(av.w);
            ffma2(acc[0][0], a0, v0); ffma2(acc[0][1], a0, v1); ffma2(acc[0][2], a0, v2);
            ffma2(acc[0][3], a0, v3); ffma2(acc[0][4], a0, v4);
            ffma2(acc[1][0], a1, v0); ffma2(acc[1][1], a1, v1); ffma2(acc[1][2], a1, v2);
            ffma2(acc[1][3], a1, v3); ffma2(acc[1][4], a1, v4);
            ffma2(acc[2][0], a2, v0); ffma2(acc[2][1], a2, v1); ffma2(acc[2][2], a2, v2);
            ffma2(acc[2][3], a2, v3); ffma2(acc[2][4], a2, v4);
            ffma2(acc[3][0], a3, v0); ffma2(acc[3][1], a3, v1); ffma2(acc[3][2], a3, v2);
            ffma2(acc[3][3], a3, v3); ffma2(acc[3][4], a3, v4);
        }
        __syncthreads();
    }
    int slot = t & 31;
    if (ks >= 2) {
        u64* dst = red + ((ks - 2) * 32 + slot) * 20;
        #pragma unroll
        for (int rr = 0; rr < 4; rr++)
            #pragma unroll
            for (int p = 0; p < 5; p++) dst[rr * 5 + p] = acc[rr][p];
    }
    __syncthreads();
    if (ks < 2) {
        const u64* src = red + (ks * 32 + slot) * 20;
        #pragma unroll
        for (int rr = 0; rr < 4; rr++)
            #pragma unroll
            for (int p = 0; p < 5; p++) {
                float2 a = up2(acc[rr][p]), b = up2(src[rr * 5 + p]);
                acc[rr][p] = pk2(a.x + b.x, a.y + b.y);
            }
    }
    __syncthreads();
    if (ks == 1) {
        u64* dst = red + slot * 20;
        #pragma unroll
        for (int rr = 0; rr < 4; rr++)
            #pragma unroll
            for (int p = 0; p < 5; p++) dst[rr * 5 + p] = acc[rr][p];
    }
    __syncthreads();
    if (ks == 0) {
        const u64* src = red + slot * 20;
        #pragma unroll
        for (int rr = 0; rr < 4; rr++) {
            int rl = rq * 4 + rr;
            float inv = g_Sinv[(i0 + rl) * NHD + h];
            #pragma unroll
            for (int p = 0; p < 5; p++) {
                float2 a = up2(acc[rr][p]), b = up2(src[rr * 5 + p]);
                float vx = (a.x + b.x) * inv, vy = (a.y + b.y) * inv;
                int c0 = cq * 10 + 2 * p;
                if (c0 < 16)     g_cat[(size_t)(i0 + rl) * 2112 + h * 16 + c0] = vx;
                else             opts[rl * 24 + (c0 - 16)] = vx;
                int c1 = c0 + 1;
                if (c1 < 16)     g_cat[(size_t)(i0 + rl) * 2112 + h * 16 + c1] = vy;
                else             opts[rl * 24 + (c1 - 16)] = vy;
            }
        }
    }
    __syncthreads();
    for (int e2 = t; e2 < 256; e2 += 128) {
        int rl = e2 >> 3, pv = e2 & 7;
        int n = i0 + rl;
        const float* pp = opts + rl * 24 + pv * 3;
        float d0 = pp[0] - r_trans[n * 15 + 0];
        float d1 = pp[1] - r_trans[n * 15 + 1];
        float d2 = pp[2] - r_trans[n * 15 + 2];
        const float* R = r_rot + n * 45;
        float o0 = R[0] * d0 + R[3] * d1 + R[6] * d2;
        float o1 = R[1] * d0 + R[4] * d1 + R[7] * d2;
        float o2 = R[2] * d0 + R[5] * d1 + R[8] * d2;
        float nm = sqrtf(o0 * o0 + o1 * o1 + o2 * o2 + 1e-8f);
        float* cb = g_cat + (size_t)n * 2112 + 192;
        int rr2 = h * 8 + pv;
        cb[rr2] = o0; cb[96 + rr2] = o1; cb[192 + rr2] = o2; cb[288 + rr2] = nm;
    }
}

// ---------------- launch ----------------
extern "C" void kernel_launch(void* const* d_in, const int* in_sizes, int n_in,
                              void* d_out, int out_size) {
    const float* s       = (const float*)d_in[0];
    const float* z       = (const float*)d_in[1];
    const float* r_rot   = (const float*)d_in[2];
    const float* r_trans = (const float*)d_in[3];
    const float* mask    = (const float*)d_in[4];
    const float* wq      = (const float*)d_in[5];
    const float* bq      = (const float*)d_in[6];
    const float* wkv     = (const float*)d_in[7];
    const float* bkv     = (const float*)d_in[8];
    const float* wqp     = (const float*)d_in[9];
    const float* bqp     = (const float*)d_in[10];
    const float* wkvp    = (const float*)d_in[11];
    const float* bkvp    = (const float*)d_in[12];
    const float* wb      = (const float*)d_in[13];
    const float* head_w  = (const float*)d_in[15];
    const float* wout    = (const float*)d_in[16];
    const float* bout    = (const float*)d_in[17];
    const float* wexp    = (const float*)d_in[18];
    const float* bexp    = (const float*)d_in[19];
    const float* ln_g    = (const float*)d_in[20];
    const float* ln_b    = (const float*)d_in[21];
    float* out = (float*)d_out;

    float *p_cat = nullptr, *p_part = nullptr;
    cudaGetSymbolAddress((void**)&p_cat,  g_cat);
    cudaGetSymbolAddress((void**)&p_part, g_part);

    static int attn_cfg = 0;
    if (!attn_cfg) {
        cudaFuncSetAttribute(k_zattn, cudaFuncAttributeMaxDynamicSharedMemorySize, ZAT_SMEM);
        cudaFuncSetAttribute(k_ov, cudaFuncAttributeMaxDynamicSharedMemorySize, OV_SMEM);
        attn_cfg = 1;
    }

    k_gemm64<<<dim3(6, 12, 2), 256>>>(s, wexp, nullptr, p_part, 384, 384, 12, 0, NRES * CSD);
    k_ln<<<768, 128>>>(bexp, ln_g, ln_b);
    k_gemm_proj<<<dim3(18, 12), 256>>>(wq, bq, wkv, bkv, wqp, bqp, wkvp, bkvp);
    k_assemble<<<96, 256>>>(r_rot, r_trans, head_w);
    k_qk<<<dim3(12, 12, 12), 256>>>(mask);
    k_zattn<<<768, 256, ZAT_SMEM>>>(z, wb);
    k_ov<<<dim3(24, 12), 128, OV_SMEM>>>(r_rot, r_trans);
    k_gemm64<<<dim3(6, 12, 4), 256>>>(p_cat, wout, nullptr, p_part, 2112, 384, 33, 0, NRES * CSD);
    k_combine<<<1152, 256>>>(bout, out);
}